// round 15
// baseline (speedup 1.0000x reference)
#include <cuda_runtime.h>
#include <cuda_bf16.h>

// Problem-fixed shapes
#define MAXN 50000
#define MAXE 600000
#define D 128
#define ED 16

typedef unsigned long long ull;

// packed fp32x2 helpers (sm_103a)
#define FMA2(d, a, b, c) \
    asm("fma.rn.f32x2 %0, %1, %2, %3;" : "=l"(d) : "l"(a), "l"(b), "l"(c))
#define PACK2(d, lo, hi) \
    asm("mov.b64 %0, {%1, %2};" : "=l"(d) \
        : "r"(__float_as_uint(lo)), "r"(__float_as_uint(hi)))

__device__ __forceinline__ float2 upk2(ull v) {
    unsigned lo, hi;
    asm("mov.b64 {%0, %1}, %2;" : "=r"(lo), "=r"(hi) : "l"(v));
    return make_float2(__uint_as_float(lo), __uint_as_float(hi));
}

// ---------------- device scratch (static zero-init; self-zeroing kernels
// maintain the zero-at-entry invariant across graph replays) ----------------
__device__ float g_agg[MAXN * D];
__device__ float g_deg[MAXN];
__device__ float g_hnew[MAXN * D];
__device__ float g_t1[MAXN * D];
__device__ float g_t2[MAXN * D];
__device__ float g_stats[3 * 256];
__device__ float g_mom[16 + 256];
__device__ float g_scale[3 * 128];
__device__ float g_shift[3 * 128];
// CSR by destination
__device__ int   g_count[MAXN];
__device__ int   g_rowptr[MAXN];
__device__ int   g_next[MAXN];
__device__ int2  g_pair[MAXE];
__device__ int   g_partial[64];

// per-block edge_index dtype probe: int64 indices < 2^32 have zero high words
__device__ __forceinline__ int probe_is64(const void* ei, int E)
{
    const ull* p = (const ull*)ei;
    int n = E < 16 ? E : 16;
    ull o = 0;
    for (int i = 0; i < n; i++) o |= p[i];
    return (o >> 32) == 0;
}

__device__ __forceinline__ int load_idx(const void* ei, long long pos, int is64)
{
    if (is64) return (int)((const long long*)ei)[pos];
    return ((const int*)ei)[pos];
}

// ---------------- fused: edge moments + dst histogram ----------------
__global__ void __launch_bounds__(256) edge_moments_hist(
    const float* __restrict__ attr, const void* __restrict__ ei,
    int E, int N, float* __restrict__ mom, int* __restrict__ count)
{
    __shared__ float sa[128 * ED];
    __shared__ int s64;
    int tid = threadIdx.x;
    if (tid == 0) s64 = probe_is64(ei, E);
    int k = tid & 15, l = tid >> 4;
    float m = 0.f, s = 0.f;
    __syncthreads();
    int is64 = s64;
    for (int base = blockIdx.x * 128; base < E; base += gridDim.x * 128) {
        int ne = min(128, E - base);
        __syncthreads();
        for (int i = tid; i < ne * ED; i += 256)
            sa[i] = attr[(long long)base * ED + i];
        for (int i = tid; i < ne; i += 256) {
            int d = load_idx(ei, (long long)E + base + i, is64);
            if ((unsigned)d < (unsigned)N) atomicAdd(&count[d], 1);
        }
        __syncthreads();
        for (int e = 0; e < ne; e++) {
            float ak = sa[e * ED + k];
            float al = sa[e * ED + l];
            m = fmaf(ak, al, m);
            if (l == 0) s += ak;
        }
    }
    atomicAdd(&mom[16 + l * 16 + k], m);
    if (l == 0) atomicAdd(&mom[k], s);
}

// ---------------- 3-kernel exclusive scan over count[N] ----------------
#define SCAN_C 1024
__global__ void __launch_bounds__(256) scan_partials(
    const int* __restrict__ count, int N, int* __restrict__ partial)
{
    __shared__ int ssum[256];
    int b = blockIdx.x, t = threadIdx.x;
    int s = 0;
#pragma unroll
    for (int j = 0; j < 4; j++) {
        int idx = b * SCAN_C + t * 4 + j;
        if (idx < N) s += count[idx];
    }
    ssum[t] = s;
    __syncthreads();
    for (int off = 128; off > 0; off >>= 1) {
        if (t < off) ssum[t] += ssum[t + off];
        __syncthreads();
    }
    if (t == 0) partial[b] = ssum[0];
}

__global__ void scan_block(int* __restrict__ partial, int nb)
{
    __shared__ int sp[64];
    int t = threadIdx.x;
    int v = (t < nb) ? partial[t] : 0;
    sp[t] = v;
    __syncthreads();
    for (int off = 1; off < 64; off <<= 1) {
        int x = (t >= off) ? sp[t - off] : 0;
        __syncthreads();
        sp[t] += x;
        __syncthreads();
    }
    if (t < nb) partial[t] = sp[t] - v;
}

// last reader of count[] — zeroes it for the next replay
__global__ void __launch_bounds__(256) scan_write(
    int* __restrict__ count, const int* __restrict__ partial, int N,
    int* __restrict__ rowptr, int* __restrict__ nxt, float* __restrict__ degf)
{
    __shared__ int svals[256];
    int b = blockIdx.x, t = threadIdx.x;
    int v[4];
    int s = 0;
#pragma unroll
    for (int j = 0; j < 4; j++) {
        int idx = b * SCAN_C + t * 4 + j;
        v[j] = (idx < N) ? count[idx] : 0;
        s += v[j];
    }
    svals[t] = s;
    __syncthreads();
    int mine = s;
    for (int off = 1; off < 256; off <<= 1) {
        int x = (t >= off) ? svals[t - off] : 0;
        __syncthreads();
        svals[t] += x;
        __syncthreads();
    }
    int exc = svals[t] - mine + partial[b];
#pragma unroll
    for (int j = 0; j < 4; j++) {
        int idx = b * SCAN_C + t * 4 + j;
        if (idx < N) {
            rowptr[idx] = exc;
            nxt[idx] = exc;
            degf[idx] = (float)v[j];
            count[idx] = 0;   // self-zero for next replay
            exc += v[j];
        }
    }
}

// ---------------- CSR fill ----------------
__global__ void __launch_bounds__(256) csr_fill(
    const void* __restrict__ ei, int E, int N, int* __restrict__ nxt,
    int2* __restrict__ pair)
{
    __shared__ int s64;
    if (threadIdx.x == 0) s64 = probe_is64(ei, E);
    __syncthreads();
    int is64 = s64;
    for (int e = blockIdx.x * blockDim.x + threadIdx.x; e < E;
         e += gridDim.x * blockDim.x) {
        int s = load_idx(ei, e, is64);
        int d = load_idx(ei, (long long)E + e, is64);
        if ((unsigned)d >= (unsigned)N || (unsigned)s >= (unsigned)N) continue;
        int pos = atomicAdd(&nxt[d], 1);
        pair[pos] = make_int2(e, s);
    }
}

// ---------------- finalize edge BN from moments (zeroes mom after read) ----
__global__ void __launch_bounds__(128) finalize_ee_bn(
    float* __restrict__ mom, const float* __restrict__ w1,
    const float* __restrict__ b1, const float* __restrict__ gamma,
    const float* __restrict__ beta, float invE,
    float* __restrict__ scale, float* __restrict__ shift)
{
    __shared__ float S[16], M[256];
    int c = threadIdx.x;
    if (c < 16) S[c] = mom[c];
    M[c] = mom[16 + c];
    M[128 + c] = mom[144 + c];
    __syncthreads();
    mom[c] = 0.f;
    mom[128 + c] = 0.f;
    if (c < 16) mom[256 + c] = 0.f;

    float wc[16];
#pragma unroll
    for (int k = 0; k < 16; k++) wc[k] = w1[k * D + c];
    float sw = 0.f;
#pragma unroll
    for (int k = 0; k < 16; k++) sw = fmaf(S[k], wc[k], sw);
    float bc = b1[c];
    float mean = sw * invE + bc;
    float q = 0.f;
#pragma unroll
    for (int k = 0; k < 16; k++) {
        float t = 0.f;
#pragma unroll
        for (int l = 0; l < 16; l++) t = fmaf(M[k * 16 + l], wc[l], t);
        q = fmaf(wc[k], t, q);
    }
    float ex2 = q * invE + 2.f * bc * sw * invE + bc * bc;
    float var = ex2 - mean * mean;
    float inv = rsqrtf(var + 1e-5f);
    float sc = gamma[c] * inv;
    scale[c] = sc;
    shift[c] = beta[c] - mean * sc;
}

// ---------------- finalize BN from colstats (zeroes stats after read) ------
__global__ void finalize_bn(float* __restrict__ stats,
                            const float* __restrict__ gamma,
                            const float* __restrict__ beta,
                            float invn, float* __restrict__ scale,
                            float* __restrict__ shift)
{
    int c = threadIdx.x;
    float sum1 = stats[c];
    float sum2 = stats[128 + c];
    stats[c] = 0.f;
    stats[128 + c] = 0.f;
    float mean = sum1 * invn;
    float var = sum2 * invn - mean * mean;
    float inv = rsqrtf(var + 1e-5f);
    float sc = gamma[c] * inv;
    scale[c] = sc;
    shift[c] = beta[c] - mean * sc;
}

// ---------------- agg gather, unroll x2, f32x2 dot products -----------------
__global__ void __launch_bounds__(256) agg_gather(
    const float* __restrict__ attr, const int* __restrict__ rowptr,
    const float* __restrict__ degf, const int2* __restrict__ pair,
    const float* __restrict__ w1, const float* __restrict__ b1,
    const float* __restrict__ scale, const float* __restrict__ shift,
    int N, float* __restrict__ agg)
{
    int lane = threadIdx.x & 31;
    int warp = threadIdx.x >> 5;
    int node = blockIdx.x * 8 + warp;
    if (node >= N) return;
    int c4 = lane * 4;

    ull wp0[ED], wp1[ED];
#pragma unroll
    for (int k = 0; k < ED; k++) {
        const longlong2 wv = *(const longlong2*)&w1[k * D + c4];
        wp0[k] = (ull)wv.x;
        wp1[k] = (ull)wv.y;
    }
    float4 bb = *(const float4*)&b1[c4];
    float4 sc = *(const float4*)&scale[c4];
    float4 sh = *(const float4*)&shift[c4];
    sh.x = fmaf(bb.x, sc.x, sh.x);
    sh.y = fmaf(bb.y, sc.y, sh.y);
    sh.z = fmaf(bb.z, sc.z, sh.z);
    sh.w = fmaf(bb.w, sc.w, sh.w);

    int base = rowptr[node];
    int cnt = (int)degf[node];
    float4 acc = make_float4(0.f, 0.f, 0.f, 0.f);
    int j = 0;
    for (; j + 2 <= cnt; j += 2) {
        int ea = pair[base + j].x;
        int eb = pair[base + j + 1].x;
        const float4* pa = (const float4*)(attr + (long long)ea * ED);
        const float4* pb = (const float4*)(attr + (long long)eb * ED);
        float4 a0 = __ldg(pa), a1 = __ldg(pa + 1), a2 = __ldg(pa + 2), a3 = __ldg(pa + 3);
        float4 b0 = __ldg(pb), b1v = __ldg(pb + 1), b2 = __ldg(pb + 2), b3 = __ldg(pb + 3);
        float av[16] = {a0.x, a0.y, a0.z, a0.w, a1.x, a1.y, a1.z, a1.w,
                        a2.x, a2.y, a2.z, a2.w, a3.x, a3.y, a3.z, a3.w};
        float bv[16] = {b0.x, b0.y, b0.z, b0.w, b1v.x, b1v.y, b1v.z, b1v.w,
                        b2.x, b2.y, b2.z, b2.w, b3.x, b3.y, b3.z, b3.w};
        ull ta0 = 0ull, ta1 = 0ull, tb0 = 0ull, tb1 = 0ull;
#pragma unroll
        for (int k = 0; k < ED; k++) {
            ull ak, bk;
            PACK2(ak, av[k], av[k]);
            PACK2(bk, bv[k], bv[k]);
            FMA2(ta0, ak, wp0[k], ta0);
            FMA2(ta1, ak, wp1[k], ta1);
            FMA2(tb0, bk, wp0[k], tb0);
            FMA2(tb1, bk, wp1[k], tb1);
        }
        float2 fa0 = upk2(ta0), fa1 = upk2(ta1);
        float2 fb0 = upk2(tb0), fb1 = upk2(tb1);
        acc.x += fmaxf(fmaf(fa0.x, sc.x, sh.x), 0.f) + fmaxf(fmaf(fb0.x, sc.x, sh.x), 0.f);
        acc.y += fmaxf(fmaf(fa0.y, sc.y, sh.y), 0.f) + fmaxf(fmaf(fb0.y, sc.y, sh.y), 0.f);
        acc.z += fmaxf(fmaf(fa1.x, sc.z, sh.z), 0.f) + fmaxf(fmaf(fb1.x, sc.z, sh.z), 0.f);
        acc.w += fmaxf(fmaf(fa1.y, sc.w, sh.w), 0.f) + fmaxf(fmaf(fb1.y, sc.w, sh.w), 0.f);
    }
    if (j < cnt) {
        int e = pair[base + j].x;
        const float4* ap = (const float4*)(attr + (long long)e * ED);
        float4 a0 = __ldg(ap), a1 = __ldg(ap + 1), a2 = __ldg(ap + 2), a3 = __ldg(ap + 3);
        float av[16] = {a0.x, a0.y, a0.z, a0.w, a1.x, a1.y, a1.z, a1.w,
                        a2.x, a2.y, a2.z, a2.w, a3.x, a3.y, a3.z, a3.w};
        ull t0 = 0ull, t1 = 0ull;
#pragma unroll
        for (int k = 0; k < ED; k++) {
            ull ak;
            PACK2(ak, av[k], av[k]);
            FMA2(t0, ak, wp0[k], t0);
            FMA2(t1, ak, wp1[k], t1);
        }
        float2 f0 = upk2(t0), f1 = upk2(t1);
        acc.x += fmaxf(fmaf(f0.x, sc.x, sh.x), 0.f);
        acc.y += fmaxf(fmaf(f0.y, sc.y, sh.y), 0.f);
        acc.z += fmaxf(fmaf(f1.x, sc.z, sh.z), 0.f);
        acc.w += fmaxf(fmaf(f1.y, sc.w, sh.w), 0.f);
    }
    *(float4*)&agg[(long long)node * D + c4] = acc;
}

// ---------------- 128-wide K SIMT GEMM (f32x2) + fused pre/post + stats -----
// MODE 0: out = A@W + hin + deg*bias
// MODE 2: out = relu(A*scale+shift)@W + bias
#define GEMM_SMEM ((128 * 132 + 128 * 128) * 4)
template <int MODE, int STATS>
__global__ void __launch_bounds__(256) gemm128(
    const float* __restrict__ A, const float* __restrict__ W,
    const float* __restrict__ bias,
    const float* __restrict__ scale, const float* __restrict__ shift,
    const float* __restrict__ hin, const float* __restrict__ degv,
    float* __restrict__ out, float* __restrict__ stats, int N)
{
    extern __shared__ float sm[];
    float* As = sm;              // transposed, padded: As[k*132 + r]
    float* Ws = sm + 128 * 132;  // Ws[k*128 + c]
    int tid = threadIdx.x;
    int row0 = blockIdx.x * 128;

    for (int i = tid; i < 128 * 128; i += 256) Ws[i] = W[i];
    for (int i = tid; i < 128 * 128; i += 256) {
        int r = i >> 7, k = i & 127;
        int row = row0 + r;
        float v = 0.f;
        if (row < N) {
            v = A[(long long)row * D + k];
            if (MODE == 2) v = fmaxf(fmaf(v, scale[k], shift[k]), 0.f);
        }
        As[k * 132 + r] = v;
    }
    __syncthreads();

    int tx = tid & 15, ty = tid >> 4;
    ull accp[8][4];
#pragma unroll
    for (int i = 0; i < 8; i++)
#pragma unroll
        for (int j = 0; j < 4; j++) accp[i][j] = 0ull;

    for (int k = 0; k < 128; k++) {
        float4 a0 = *(const float4*)&As[k * 132 + ty * 8];
        float4 a1 = *(const float4*)&As[k * 132 + ty * 8 + 4];
        longlong2 b01 = *(const longlong2*)&Ws[k * 128 + tx * 8];
        longlong2 b23 = *(const longlong2*)&Ws[k * 128 + tx * 8 + 4];
        ull bp[4] = {(ull)b01.x, (ull)b01.y, (ull)b23.x, (ull)b23.y};
        float a[8] = {a0.x, a0.y, a0.z, a0.w, a1.x, a1.y, a1.z, a1.w};
#pragma unroll
        for (int i = 0; i < 8; i++) {
            ull ai;
            PACK2(ai, a[i], a[i]);
#pragma unroll
            for (int j = 0; j < 4; j++)
                FMA2(accp[i][j], ai, bp[j], accp[i][j]);
        }
    }

    float bs[8];
#pragma unroll
    for (int j = 0; j < 8; j++) bs[j] = bias[tx * 8 + j];

    float s1[8], s2[8];
#pragma unroll
    for (int j = 0; j < 8; j++) { s1[j] = 0.f; s2[j] = 0.f; }

#pragma unroll
    for (int i = 0; i < 8; i++) {
        int row = row0 + ty * 8 + i;
        if (row < N) {
            float o[8];
#pragma unroll
            for (int j = 0; j < 4; j++) {
                float2 f = upk2(accp[i][j]);
                o[j * 2] = f.x;
                o[j * 2 + 1] = f.y;
            }
            if (MODE == 0) {
                float dg = degv[row];
                float4 h0 = *(const float4*)&hin[(long long)row * D + tx * 8];
                float4 h1 = *(const float4*)&hin[(long long)row * D + tx * 8 + 4];
                float hh[8] = {h0.x, h0.y, h0.z, h0.w, h1.x, h1.y, h1.z, h1.w};
#pragma unroll
                for (int j = 0; j < 8; j++) o[j] += hh[j] + dg * bs[j];
            } else {
#pragma unroll
                for (int j = 0; j < 8; j++) o[j] += bs[j];
            }
            if (STATS) {
#pragma unroll
                for (int j = 0; j < 8; j++) {
                    s1[j] += o[j];
                    s2[j] = fmaf(o[j], o[j], s2[j]);
                }
            }
            *(float4*)&out[(long long)row * D + tx * 8] = make_float4(o[0], o[1], o[2], o[3]);
            *(float4*)&out[(long long)row * D + tx * 8 + 4] = make_float4(o[4], o[5], o[6], o[7]);
        }
    }

    if (STATS) {
        __syncthreads();
        float* p1 = sm;
        float* p2 = sm + 2048;
#pragma unroll
        for (int j = 0; j < 8; j++) {
            p1[ty * 128 + tx * 8 + j] = s1[j];
            p2[ty * 128 + tx * 8 + j] = s2[j];
        }
        __syncthreads();
        if (tid < 128) {
            float a = 0.f, b = 0.f;
#pragma unroll
            for (int r = 0; r < 16; r++) {
                a += p1[r * 128 + tid];
                b += p2[r * 128 + tid];
            }
            atomicAdd(&stats[tid], a);
            atomicAdd(&stats[128 + tid], b);
        }
    }
}

// ---------------- GEMM1 with fused neighbor gather in A-staging -------------
// staged A row = hnew[row] + sum_{e: dst=row} hnew[src_e]; out = A@W + bias
__global__ void __launch_bounds__(256) gemm_t1(
    const float* __restrict__ hnew, const int* __restrict__ rowptr,
    const float* __restrict__ degf, const int2* __restrict__ pair,
    const float* __restrict__ W, const float* __restrict__ bias,
    float* __restrict__ out, float* __restrict__ stats, int N)
{
    extern __shared__ float sm[];
    float* As = sm;              // transposed, padded
    float* Ws = sm + 128 * 132;
    int tid = threadIdx.x;
    int row0 = blockIdx.x * 128;
    int lane = tid & 31;
    int warp = tid >> 5;
    int c4g = lane * 4;

    for (int i = tid; i < 128 * 128; i += 256) Ws[i] = W[i];

    // fused gather staging: warp per row, 16 rows per warp
    for (int rr = warp; rr < 128; rr += 8) {
        int row = row0 + rr;
        float4 acc0 = make_float4(0.f, 0.f, 0.f, 0.f);
        float4 acc1 = make_float4(0.f, 0.f, 0.f, 0.f);
        if (row < N) {
            acc0 = *(const float4*)&hnew[(long long)row * D + c4g];
            int base = rowptr[row];
            int cnt = (int)degf[row];
            int j = 0;
            for (; j + 2 <= cnt; j += 2) {
                int s0 = pair[base + j].y;
                int s1 = pair[base + j + 1].y;
                float4 v0 = __ldg((const float4*)&hnew[(long long)s0 * D + c4g]);
                float4 v1 = __ldg((const float4*)&hnew[(long long)s1 * D + c4g]);
                acc0.x += v0.x; acc0.y += v0.y; acc0.z += v0.z; acc0.w += v0.w;
                acc1.x += v1.x; acc1.y += v1.y; acc1.z += v1.z; acc1.w += v1.w;
            }
            if (j < cnt) {
                int s = pair[base + j].y;
                float4 v = __ldg((const float4*)&hnew[(long long)s * D + c4g]);
                acc0.x += v.x; acc0.y += v.y; acc0.z += v.z; acc0.w += v.w;
            }
            acc0.x += acc1.x; acc0.y += acc1.y; acc0.z += acc1.z; acc0.w += acc1.w;
        }
        As[(c4g + 0) * 132 + rr] = acc0.x;
        As[(c4g + 1) * 132 + rr] = acc0.y;
        As[(c4g + 2) * 132 + rr] = acc0.z;
        As[(c4g + 3) * 132 + rr] = acc0.w;
    }
    __syncthreads();

    int tx = tid & 15, ty = tid >> 4;
    ull accp[8][4];
#pragma unroll
    for (int i = 0; i < 8; i++)
#pragma unroll
        for (int j = 0; j < 4; j++) accp[i][j] = 0ull;

    for (int k = 0; k < 128; k++) {
        float4 a0 = *(const float4*)&As[k * 132 + ty * 8];
        float4 a1 = *(const float4*)&As[k * 132 + ty * 8 + 4];
        longlong2 b01 = *(const longlong2*)&Ws[k * 128 + tx * 8];
        longlong2 b23 = *(const longlong2*)&Ws[k * 128 + tx * 8 + 4];
        ull bp[4] = {(ull)b01.x, (ull)b01.y, (ull)b23.x, (ull)b23.y};
        float a[8] = {a0.x, a0.y, a0.z, a0.w, a1.x, a1.y, a1.z, a1.w};
#pragma unroll
        for (int i = 0; i < 8; i++) {
            ull ai;
            PACK2(ai, a[i], a[i]);
#pragma unroll
            for (int j = 0; j < 4; j++)
                FMA2(accp[i][j], ai, bp[j], accp[i][j]);
        }
    }

    float bs[8];
#pragma unroll
    for (int j = 0; j < 8; j++) bs[j] = bias[tx * 8 + j];

    float s1[8], s2[8];
#pragma unroll
    for (int j = 0; j < 8; j++) { s1[j] = 0.f; s2[j] = 0.f; }

#pragma unroll
    for (int i = 0; i < 8; i++) {
        int row = row0 + ty * 8 + i;
        if (row < N) {
            float o[8];
#pragma unroll
            for (int j = 0; j < 4; j++) {
                float2 f = upk2(accp[i][j]);
                o[j * 2] = f.x + bs[j * 2];
                o[j * 2 + 1] = f.y + bs[j * 2 + 1];
            }
#pragma unroll
            for (int j = 0; j < 8; j++) {
                s1[j] += o[j];
                s2[j] = fmaf(o[j], o[j], s2[j]);
            }
            *(float4*)&out[(long long)row * D + tx * 8] = make_float4(o[0], o[1], o[2], o[3]);
            *(float4*)&out[(long long)row * D + tx * 8 + 4] = make_float4(o[4], o[5], o[6], o[7]);
        }
    }

    __syncthreads();
    float* p1 = sm;
    float* p2 = sm + 2048;
#pragma unroll
    for (int j = 0; j < 8; j++) {
        p1[ty * 128 + tx * 8 + j] = s1[j];
        p2[ty * 128 + tx * 8 + j] = s2[j];
    }
    __syncthreads();
    if (tid < 128) {
        float a = 0.f, b = 0.f;
#pragma unroll
        for (int r = 0; r < 16; r++) {
            a += p1[r * 128 + tid];
            b += p2[r * 128 + tid];
        }
        atomicAdd(&stats[tid], a);
        atomicAdd(&stats[128 + tid], b);
    }
}

// ---------------- final eltwise: out = relu(bn(t2)) ----------------
__global__ void __launch_bounds__(256) bn_relu_out(
    const float* __restrict__ t2, const float* __restrict__ scale,
    const float* __restrict__ shift, float* __restrict__ out, int N)
{
    int total4 = N * 32;
    for (int idx = blockIdx.x * blockDim.x + threadIdx.x; idx < total4;
         idx += gridDim.x * blockDim.x) {
        int c4 = (idx & 31) * 4;
        float4 v = *(const float4*)&t2[(long long)idx * 4];
        float4 sc = *(const float4*)&scale[c4];
        float4 sh = *(const float4*)&shift[c4];
        float4 o;
        o.x = fmaxf(fmaf(v.x, sc.x, sh.x), 0.f);
        o.y = fmaxf(fmaf(v.y, sc.y, sh.y), 0.f);
        o.z = fmaxf(fmaf(v.z, sc.z, sh.z), 0.f);
        o.w = fmaxf(fmaf(v.w, sc.w, sh.w), 0.f);
        *(float4*)&out[(long long)idx * 4] = o;
    }
}

// ---------------- launch ----------------
extern "C" void kernel_launch(void* const* d_in, const int* in_sizes, int n_in,
                              void* d_out, int out_size)
{
    const float* h        = (const float*)d_in[0];
    const void*  ei       = d_in[1];
    const float* attr     = (const float*)d_in[2];
    const float* ee_w1    = (const float*)d_in[3];
    const float* ee_b1    = (const float*)d_in[4];
    const float* ee_g1    = (const float*)d_in[5];
    const float* ee_bb1   = (const float*)d_in[6];
    const float* ee_w2    = (const float*)d_in[7];
    const float* ee_b2    = (const float*)d_in[8];
    const float* mlp_w1   = (const float*)d_in[9];
    const float* mlp_b1   = (const float*)d_in[10];
    const float* mlp_g1   = (const float*)d_in[11];
    const float* mlp_bb1  = (const float*)d_in[12];
    const float* mlp_w2   = (const float*)d_in[13];
    const float* mlp_b2   = (const float*)d_in[14];
    const float* mlp_g2   = (const float*)d_in[15];
    const float* mlp_bb2  = (const float*)d_in[16];

    int N = in_sizes[0] / D;
    int E = in_sizes[1] / 2;
    float* out = (float*)d_out;

    float *p_agg, *p_deg, *p_hnew, *p_t1, *p_t2, *p_stats, *p_mom, *p_scale, *p_shift;
    int *p_count, *p_rowptr, *p_next, *p_partial;
    int2 *p_pair;
    cudaGetSymbolAddress((void**)&p_agg, g_agg);
    cudaGetSymbolAddress((void**)&p_deg, g_deg);
    cudaGetSymbolAddress((void**)&p_hnew, g_hnew);
    cudaGetSymbolAddress((void**)&p_t1, g_t1);
    cudaGetSymbolAddress((void**)&p_t2, g_t2);
    cudaGetSymbolAddress((void**)&p_stats, g_stats);
    cudaGetSymbolAddress((void**)&p_mom, g_mom);
    cudaGetSymbolAddress((void**)&p_scale, g_scale);
    cudaGetSymbolAddress((void**)&p_shift, g_shift);
    cudaGetSymbolAddress((void**)&p_count, g_count);
    cudaGetSymbolAddress((void**)&p_rowptr, g_rowptr);
    cudaGetSymbolAddress((void**)&p_next, g_next);
    cudaGetSymbolAddress((void**)&p_pair, g_pair);
    cudaGetSymbolAddress((void**)&p_partial, g_partial);

    cudaFuncSetAttribute(gemm128<0,0>, cudaFuncAttributeMaxDynamicSharedMemorySize, GEMM_SMEM);
    cudaFuncSetAttribute(gemm_t1, cudaFuncAttributeMaxDynamicSharedMemorySize, GEMM_SMEM);
    cudaFuncSetAttribute(gemm128<2,1>, cudaFuncAttributeMaxDynamicSharedMemorySize, GEMM_SMEM);

    int tiles = (N + 127) / 128;
    int nscan = (N + SCAN_C - 1) / SCAN_C;
    int ngather = (N + 7) / 8;

    // fused edge moments + dst histogram (count[] pre-zeroed by prior replay)
    edge_moments_hist<<<1184, 256>>>(attr, ei, E, N, p_mom, p_count);
    finalize_ee_bn<<<1, 128>>>(p_mom, ee_w1, ee_b1, ee_g1, ee_bb1,
                               1.0f / (float)E, p_scale, p_shift);

    // CSR build (by dst)
    scan_partials<<<nscan, 256>>>(p_count, N, p_partial);
    scan_block<<<1, 64>>>(p_partial, nscan);
    scan_write<<<nscan, 256>>>(p_count, p_partial, N, p_rowptr, p_next, p_deg);
    csr_fill<<<1184, 256>>>(ei, E, N, p_next, p_pair);

    // agg = segment_sum(relu(BN(attr@W1)), dst)
    agg_gather<<<ngather, 256>>>(attr, p_rowptr, p_deg, p_pair,
                                 ee_w1, ee_b1, p_scale, p_shift, N, p_agg);

    // h_new = h + agg@ee_w2 + deg*ee_b2
    gemm128<0,0><<<tiles, 256, GEMM_SMEM>>>(p_agg, ee_w2, ee_b2,
                                            nullptr, nullptr, h, p_deg, p_hnew,
                                            nullptr, N);

    // t1 = (h_new + S.h_new) @ mlp_w1 + b1  (neigh gather fused into staging)
    gemm_t1<<<tiles, 256, GEMM_SMEM>>>(p_hnew, p_rowptr, p_deg, p_pair,
                                       mlp_w1, mlp_b1, p_t1, p_stats + 256, N);
    finalize_bn<<<1, 128>>>(p_stats + 256, mlp_g1, mlp_bb1, 1.0f / (float)N,
                            p_scale + 128, p_shift + 128);

    // t2 = relu(bn(t1)) @ mlp_w2 + b2   (+ fused colstats)
    gemm128<2,1><<<tiles, 256, GEMM_SMEM>>>(p_t1, mlp_w2, mlp_b2,
                                            p_scale + 128, p_shift + 128,
                                            nullptr, nullptr, p_t2,
                                            p_stats + 512, N);
    finalize_bn<<<1, 128>>>(p_stats + 512, mlp_g2, mlp_bb2, 1.0f / (float)N,
                            p_scale + 256, p_shift + 256);

    // out = relu(bn(t2))
    int g = min((N * 32 + 255) / 256, 4096);
    bn_relu_out<<<g, 256>>>(p_t2, p_scale + 256, p_shift + 256, out, N);
}

// round 16
// speedup vs baseline: 1.0554x; 1.0554x over previous
#include <cuda_runtime.h>
#include <cuda_bf16.h>

// Problem-fixed shapes
#define MAXN 50000
#define MAXE 600000
#define D 128
#define ED 16

typedef unsigned long long ull;

// packed fp32x2 helpers (sm_103a)
#define FMA2(d, a, b, c) \
    asm("fma.rn.f32x2 %0, %1, %2, %3;" : "=l"(d) : "l"(a), "l"(b), "l"(c))
#define PACK2(d, lo, hi) \
    asm("mov.b64 %0, {%1, %2};" : "=l"(d) \
        : "r"(__float_as_uint(lo)), "r"(__float_as_uint(hi)))

__device__ __forceinline__ float2 upk2(ull v) {
    unsigned lo, hi;
    asm("mov.b64 {%0, %1}, %2;" : "=r"(lo), "=r"(hi) : "l"(v));
    return make_float2(__uint_as_float(lo), __uint_as_float(hi));
}

// ---------------- device scratch (static zero-init; self-zeroing kernels
// maintain the zero-at-entry invariant across graph replays) ----------------
__device__ float g_agg[MAXN * D];
__device__ float g_deg[MAXN];
__device__ float g_hnew[MAXN * D];
__device__ float g_neigh[MAXN * D];
__device__ float g_t1[MAXN * D];
__device__ float g_t2[MAXN * D];
__device__ float g_stats[3 * 256];   // [256..511]=BN1 sums, [512..767]=BN2 sums
__device__ float g_mom[16 + 256];
__device__ float g_scale[3 * 128];
__device__ float g_shift[3 * 128];
// CSR by destination
__device__ int   g_count[MAXN];
__device__ int   g_rowptr[MAXN];
__device__ int   g_next[MAXN];
__device__ int2  g_pair[MAXE];
__device__ int   g_partial[64];

// per-block edge_index dtype probe: int64 indices < 2^32 have zero high words
__device__ __forceinline__ int probe_is64(const void* ei, int E)
{
    const ull* p = (const ull*)ei;
    int n = E < 16 ? E : 16;
    ull o = 0;
    for (int i = 0; i < n; i++) o |= p[i];
    return (o >> 32) == 0;
}

__device__ __forceinline__ int load_idx(const void* ei, long long pos, int is64)
{
    if (is64) return (int)((const long long*)ei)[pos];
    return ((const int*)ei)[pos];
}

// ---------------- fused: edge moments + dst histogram ----------------
// block 0 also zeroes stats[512..767] (read by previous replay's bn_relu_out,
// written later this replay by gemm2's epilogue)
__global__ void __launch_bounds__(256) edge_moments_hist(
    const float* __restrict__ attr, const void* __restrict__ ei,
    int E, int N, float* __restrict__ mom, int* __restrict__ count,
    float* __restrict__ stats2)
{
    __shared__ float sa[128 * ED];
    __shared__ int s64;
    int tid = threadIdx.x;
    if (tid == 0) s64 = probe_is64(ei, E);
    if (blockIdx.x == 0) stats2[tid] = 0.f;
    int k = tid & 15, l = tid >> 4;
    float m = 0.f, s = 0.f;
    __syncthreads();
    int is64 = s64;
    for (int base = blockIdx.x * 128; base < E; base += gridDim.x * 128) {
        int ne = min(128, E - base);
        __syncthreads();
        for (int i = tid; i < ne * ED; i += 256)
            sa[i] = attr[(long long)base * ED + i];
        for (int i = tid; i < ne; i += 256) {
            int d = load_idx(ei, (long long)E + base + i, is64);
            if ((unsigned)d < (unsigned)N) atomicAdd(&count[d], 1);
        }
        __syncthreads();
        for (int e = 0; e < ne; e++) {
            float ak = sa[e * ED + k];
            float al = sa[e * ED + l];
            m = fmaf(ak, al, m);
            if (l == 0) s += ak;
        }
    }
    atomicAdd(&mom[16 + l * 16 + k], m);
    if (l == 0) atomicAdd(&mom[k], s);
}

// ---------------- 3-kernel exclusive scan over count[N] ----------------
#define SCAN_C 1024
__global__ void __launch_bounds__(256) scan_partials(
    const int* __restrict__ count, int N, int* __restrict__ partial)
{
    __shared__ int ssum[256];
    int b = blockIdx.x, t = threadIdx.x;
    int s = 0;
#pragma unroll
    for (int j = 0; j < 4; j++) {
        int idx = b * SCAN_C + t * 4 + j;
        if (idx < N) s += count[idx];
    }
    ssum[t] = s;
    __syncthreads();
    for (int off = 128; off > 0; off >>= 1) {
        if (t < off) ssum[t] += ssum[t + off];
        __syncthreads();
    }
    if (t == 0) partial[b] = ssum[0];
}

__global__ void scan_block(int* __restrict__ partial, int nb)
{
    __shared__ int sp[64];
    int t = threadIdx.x;
    int v = (t < nb) ? partial[t] : 0;
    sp[t] = v;
    __syncthreads();
    for (int off = 1; off < 64; off <<= 1) {
        int x = (t >= off) ? sp[t - off] : 0;
        __syncthreads();
        sp[t] += x;
        __syncthreads();
    }
    if (t < nb) partial[t] = sp[t] - v;
}

// last reader of count[] — zeroes it for the next replay
__global__ void __launch_bounds__(256) scan_write(
    int* __restrict__ count, const int* __restrict__ partial, int N,
    int* __restrict__ rowptr, int* __restrict__ nxt, float* __restrict__ degf)
{
    __shared__ int svals[256];
    int b = blockIdx.x, t = threadIdx.x;
    int v[4];
    int s = 0;
#pragma unroll
    for (int j = 0; j < 4; j++) {
        int idx = b * SCAN_C + t * 4 + j;
        v[j] = (idx < N) ? count[idx] : 0;
        s += v[j];
    }
    svals[t] = s;
    __syncthreads();
    int mine = s;
    for (int off = 1; off < 256; off <<= 1) {
        int x = (t >= off) ? svals[t - off] : 0;
        __syncthreads();
        svals[t] += x;
        __syncthreads();
    }
    int exc = svals[t] - mine + partial[b];
#pragma unroll
    for (int j = 0; j < 4; j++) {
        int idx = b * SCAN_C + t * 4 + j;
        if (idx < N) {
            rowptr[idx] = exc;
            nxt[idx] = exc;
            degf[idx] = (float)v[j];
            count[idx] = 0;   // self-zero for next replay
            exc += v[j];
        }
    }
}

// ---------------- CSR fill ----------------
__global__ void __launch_bounds__(256) csr_fill(
    const void* __restrict__ ei, int E, int N, int* __restrict__ nxt,
    int2* __restrict__ pair)
{
    __shared__ int s64;
    if (threadIdx.x == 0) s64 = probe_is64(ei, E);
    __syncthreads();
    int is64 = s64;
    for (int e = blockIdx.x * blockDim.x + threadIdx.x; e < E;
         e += gridDim.x * blockDim.x) {
        int s = load_idx(ei, e, is64);
        int d = load_idx(ei, (long long)E + e, is64);
        if ((unsigned)d >= (unsigned)N || (unsigned)s >= (unsigned)N) continue;
        int pos = atomicAdd(&nxt[d], 1);
        pair[pos] = make_int2(e, s);
    }
}

// ---------------- finalize edge BN from moments (zeroes mom after read) ----
__global__ void __launch_bounds__(128) finalize_ee_bn(
    float* __restrict__ mom, const float* __restrict__ w1,
    const float* __restrict__ b1, const float* __restrict__ gamma,
    const float* __restrict__ beta, float invE,
    float* __restrict__ scale, float* __restrict__ shift)
{
    __shared__ float S[16], M[256];
    int c = threadIdx.x;
    if (c < 16) S[c] = mom[c];
    M[c] = mom[16 + c];
    M[128 + c] = mom[144 + c];
    __syncthreads();
    mom[c] = 0.f;
    mom[128 + c] = 0.f;
    if (c < 16) mom[256 + c] = 0.f;

    float wc[16];
#pragma unroll
    for (int k = 0; k < 16; k++) wc[k] = w1[k * D + c];
    float sw = 0.f;
#pragma unroll
    for (int k = 0; k < 16; k++) sw = fmaf(S[k], wc[k], sw);
    float bc = b1[c];
    float mean = sw * invE + bc;
    float q = 0.f;
#pragma unroll
    for (int k = 0; k < 16; k++) {
        float t = 0.f;
#pragma unroll
        for (int l = 0; l < 16; l++) t = fmaf(M[k * 16 + l], wc[l], t);
        q = fmaf(wc[k], t, q);
    }
    float ex2 = q * invE + 2.f * bc * sw * invE + bc * bc;
    float var = ex2 - mean * mean;
    float inv = rsqrtf(var + 1e-5f);
    float sc = gamma[c] * inv;
    scale[c] = sc;
    shift[c] = beta[c] - mean * sc;
}

// ---------------- agg gather, unroll x2, f32x2 dot products -----------------
__global__ void __launch_bounds__(256) agg_gather(
    const float* __restrict__ attr, const int* __restrict__ rowptr,
    const float* __restrict__ degf, const int2* __restrict__ pair,
    const float* __restrict__ w1, const float* __restrict__ b1,
    const float* __restrict__ scale, const float* __restrict__ shift,
    int N, float* __restrict__ agg)
{
    int lane = threadIdx.x & 31;
    int warp = threadIdx.x >> 5;
    int node = blockIdx.x * 8 + warp;
    if (node >= N) return;
    int c4 = lane * 4;

    ull wp0[ED], wp1[ED];
#pragma unroll
    for (int k = 0; k < ED; k++) {
        const longlong2 wv = *(const longlong2*)&w1[k * D + c4];
        wp0[k] = (ull)wv.x;
        wp1[k] = (ull)wv.y;
    }
    float4 bb = *(const float4*)&b1[c4];
    float4 sc = *(const float4*)&scale[c4];
    float4 sh = *(const float4*)&shift[c4];
    sh.x = fmaf(bb.x, sc.x, sh.x);
    sh.y = fmaf(bb.y, sc.y, sh.y);
    sh.z = fmaf(bb.z, sc.z, sh.z);
    sh.w = fmaf(bb.w, sc.w, sh.w);

    int base = rowptr[node];
    int cnt = (int)degf[node];
    float4 acc = make_float4(0.f, 0.f, 0.f, 0.f);
    int j = 0;
    for (; j + 2 <= cnt; j += 2) {
        int ea = pair[base + j].x;
        int eb = pair[base + j + 1].x;
        const float4* pa = (const float4*)(attr + (long long)ea * ED);
        const float4* pb = (const float4*)(attr + (long long)eb * ED);
        float4 a0 = __ldg(pa), a1 = __ldg(pa + 1), a2 = __ldg(pa + 2), a3 = __ldg(pa + 3);
        float4 b0 = __ldg(pb), b1v = __ldg(pb + 1), b2 = __ldg(pb + 2), b3 = __ldg(pb + 3);
        float av[16] = {a0.x, a0.y, a0.z, a0.w, a1.x, a1.y, a1.z, a1.w,
                        a2.x, a2.y, a2.z, a2.w, a3.x, a3.y, a3.z, a3.w};
        float bv[16] = {b0.x, b0.y, b0.z, b0.w, b1v.x, b1v.y, b1v.z, b1v.w,
                        b2.x, b2.y, b2.z, b2.w, b3.x, b3.y, b3.z, b3.w};
        ull ta0 = 0ull, ta1 = 0ull, tb0 = 0ull, tb1 = 0ull;
#pragma unroll
        for (int k = 0; k < ED; k++) {
            ull ak, bk;
            PACK2(ak, av[k], av[k]);
            PACK2(bk, bv[k], bv[k]);
            FMA2(ta0, ak, wp0[k], ta0);
            FMA2(ta1, ak, wp1[k], ta1);
            FMA2(tb0, bk, wp0[k], tb0);
            FMA2(tb1, bk, wp1[k], tb1);
        }
        float2 fa0 = upk2(ta0), fa1 = upk2(ta1);
        float2 fb0 = upk2(tb0), fb1 = upk2(tb1);
        acc.x += fmaxf(fmaf(fa0.x, sc.x, sh.x), 0.f) + fmaxf(fmaf(fb0.x, sc.x, sh.x), 0.f);
        acc.y += fmaxf(fmaf(fa0.y, sc.y, sh.y), 0.f) + fmaxf(fmaf(fb0.y, sc.y, sh.y), 0.f);
        acc.z += fmaxf(fmaf(fa1.x, sc.z, sh.z), 0.f) + fmaxf(fmaf(fb1.x, sc.z, sh.z), 0.f);
        acc.w += fmaxf(fmaf(fa1.y, sc.w, sh.w), 0.f) + fmaxf(fmaf(fb1.y, sc.w, sh.w), 0.f);
    }
    if (j < cnt) {
        int e = pair[base + j].x;
        const float4* ap = (const float4*)(attr + (long long)e * ED);
        float4 a0 = __ldg(ap), a1 = __ldg(ap + 1), a2 = __ldg(ap + 2), a3 = __ldg(ap + 3);
        float av[16] = {a0.x, a0.y, a0.z, a0.w, a1.x, a1.y, a1.z, a1.w,
                        a2.x, a2.y, a2.z, a2.w, a3.x, a3.y, a3.z, a3.w};
        ull t0 = 0ull, t1 = 0ull;
#pragma unroll
        for (int k = 0; k < ED; k++) {
            ull ak;
            PACK2(ak, av[k], av[k]);
            FMA2(t0, ak, wp0[k], t0);
            FMA2(t1, ak, wp1[k], t1);
        }
        float2 f0 = upk2(t0), f1 = upk2(t1);
        acc.x += fmaxf(fmaf(f0.x, sc.x, sh.x), 0.f);
        acc.y += fmaxf(fmaf(f0.y, sc.y, sh.y), 0.f);
        acc.z += fmaxf(fmaf(f1.x, sc.z, sh.z), 0.f);
        acc.w += fmaxf(fmaf(f1.y, sc.w, sh.w), 0.f);
    }
    *(float4*)&agg[(long long)node * D + c4] = acc;
}

// ---------------- neigh gather, unroll x2 ----------------
__global__ void __launch_bounds__(256) neigh_gather(
    const float* __restrict__ hnew, const int* __restrict__ rowptr,
    const float* __restrict__ degf, const int2* __restrict__ pair,
    int N, float* __restrict__ neigh)
{
    int lane = threadIdx.x & 31;
    int warp = threadIdx.x >> 5;
    int node = blockIdx.x * 8 + warp;
    if (node >= N) return;
    int c4 = lane * 4;
    int base = rowptr[node];
    int cnt = (int)degf[node];
    float4 acc0 = make_float4(0.f, 0.f, 0.f, 0.f);
    float4 acc1 = make_float4(0.f, 0.f, 0.f, 0.f);
    int j = 0;
    for (; j + 2 <= cnt; j += 2) {
        int s0 = pair[base + j].y;
        int s1 = pair[base + j + 1].y;
        float4 v0 = __ldg((const float4*)&hnew[(long long)s0 * D + c4]);
        float4 v1 = __ldg((const float4*)&hnew[(long long)s1 * D + c4]);
        acc0.x += v0.x; acc0.y += v0.y; acc0.z += v0.z; acc0.w += v0.w;
        acc1.x += v1.x; acc1.y += v1.y; acc1.z += v1.z; acc1.w += v1.w;
    }
    if (j < cnt) {
        int s = pair[base + j].y;
        float4 v = __ldg((const float4*)&hnew[(long long)s * D + c4]);
        acc0.x += v.x; acc0.y += v.y; acc0.z += v.z; acc0.w += v.w;
    }
    acc0.x += acc1.x; acc0.y += acc1.y; acc0.z += acc1.z; acc0.w += acc1.w;
    *(float4*)&neigh[(long long)node * D + c4] = acc0;
}

// ---------------- 128-wide K SIMT GEMM (f32x2) + fused pre/post + stats -----
// MODE 0: out = A@W + hin + deg*bias
// MODE 1: out = (A + A2)@W + bias
// MODE 2: out = relu(A*bnscale+bnshift)@W + bias  (BN finalize inlined from stats_in)
#define GEMM_SMEM ((128 * 132 + 128 * 128 + 256) * 4)
template <int MODE, int STATS>
__global__ void __launch_bounds__(256) gemm128(
    const float* __restrict__ A, const float* __restrict__ A2,
    const float* __restrict__ W, const float* __restrict__ bias,
    const float* __restrict__ stats_in, const float* __restrict__ gamma,
    const float* __restrict__ beta, float invn,
    const float* __restrict__ hin, const float* __restrict__ degv,
    float* __restrict__ out, float* __restrict__ stats, int N)
{
    extern __shared__ float sm[];
    float* As = sm;                      // transposed, padded: As[k*132 + r]
    float* Ws = sm + 128 * 132;          // Ws[k*128 + c]
    float* sscale = Ws + 128 * 128;      // [128]
    float* sshift = sscale + 128;        // [128]
    int tid = threadIdx.x;
    int row0 = blockIdx.x * 128;

    if (MODE == 2) {
        if (tid < 128) {
            float mean = stats_in[tid] * invn;
            float var = stats_in[128 + tid] * invn - mean * mean;
            float inv = rsqrtf(var + 1e-5f);
            float scv = gamma[tid] * inv;
            sscale[tid] = scv;
            sshift[tid] = beta[tid] - mean * scv;
        }
        __syncthreads();
    }

    for (int i = tid; i < 128 * 128; i += 256) Ws[i] = W[i];
    for (int i = tid; i < 128 * 128; i += 256) {
        int r = i >> 7, k = i & 127;
        int row = row0 + r;
        float v = 0.f;
        if (row < N) {
            v = A[(long long)row * D + k];
            if (MODE == 1) v += A2[(long long)row * D + k];
            if (MODE == 2) v = fmaxf(fmaf(v, sscale[k], sshift[k]), 0.f);
        }
        As[k * 132 + r] = v;
    }
    __syncthreads();

    int tx = tid & 15, ty = tid >> 4;
    ull accp[8][4];
#pragma unroll
    for (int i = 0; i < 8; i++)
#pragma unroll
        for (int j = 0; j < 4; j++) accp[i][j] = 0ull;

    for (int k = 0; k < 128; k++) {
        float4 a0 = *(const float4*)&As[k * 132 + ty * 8];
        float4 a1 = *(const float4*)&As[k * 132 + ty * 8 + 4];
        longlong2 b01 = *(const longlong2*)&Ws[k * 128 + tx * 8];
        longlong2 b23 = *(const longlong2*)&Ws[k * 128 + tx * 8 + 4];
        ull bp[4] = {(ull)b01.x, (ull)b01.y, (ull)b23.x, (ull)b23.y};
        float a[8] = {a0.x, a0.y, a0.z, a0.w, a1.x, a1.y, a1.z, a1.w};
#pragma unroll
        for (int i = 0; i < 8; i++) {
            ull ai;
            PACK2(ai, a[i], a[i]);
#pragma unroll
            for (int j = 0; j < 4; j++)
                FMA2(accp[i][j], ai, bp[j], accp[i][j]);
        }
    }

    float bs[8];
#pragma unroll
    for (int j = 0; j < 8; j++) bs[j] = bias[tx * 8 + j];

    float s1[8], s2[8];
#pragma unroll
    for (int j = 0; j < 8; j++) { s1[j] = 0.f; s2[j] = 0.f; }

#pragma unroll
    for (int i = 0; i < 8; i++) {
        int row = row0 + ty * 8 + i;
        if (row < N) {
            float o[8];
#pragma unroll
            for (int j = 0; j < 4; j++) {
                float2 f = upk2(accp[i][j]);
                o[j * 2] = f.x;
                o[j * 2 + 1] = f.y;
            }
            if (MODE == 0) {
                float dg = degv[row];
                float4 h0 = *(const float4*)&hin[(long long)row * D + tx * 8];
                float4 h1 = *(const float4*)&hin[(long long)row * D + tx * 8 + 4];
                float hh[8] = {h0.x, h0.y, h0.z, h0.w, h1.x, h1.y, h1.z, h1.w};
#pragma unroll
                for (int j = 0; j < 8; j++) o[j] += hh[j] + dg * bs[j];
            } else {
#pragma unroll
                for (int j = 0; j < 8; j++) o[j] += bs[j];
            }
            if (STATS) {
#pragma unroll
                for (int j = 0; j < 8; j++) {
                    s1[j] += o[j];
                    s2[j] = fmaf(o[j], o[j], s2[j]);
                }
            }
            *(float4*)&out[(long long)row * D + tx * 8] = make_float4(o[0], o[1], o[2], o[3]);
            *(float4*)&out[(long long)row * D + tx * 8 + 4] = make_float4(o[4], o[5], o[6], o[7]);
        }
    }

    if (STATS) {
        __syncthreads();
        float* p1 = sm;
        float* p2 = sm + 2048;
#pragma unroll
        for (int j = 0; j < 8; j++) {
            p1[ty * 128 + tx * 8 + j] = s1[j];
            p2[ty * 128 + tx * 8 + j] = s2[j];
        }
        __syncthreads();
        if (tid < 128) {
            float a = 0.f, b = 0.f;
#pragma unroll
            for (int r = 0; r < 16; r++) {
                a += p1[r * 128 + tid];
                b += p2[r * 128 + tid];
            }
            atomicAdd(&stats[tid], a);
            atomicAdd(&stats[128 + tid], b);
        }
    }
}

// ---------------- final eltwise: out = relu(bn(t2)), finalize inlined -------
// block 0 zeroes stats1 (BN1 sums, last read by gemm2's prologue) for next replay
__global__ void __launch_bounds__(256) bn_relu_out(
    const float* __restrict__ t2, const float* __restrict__ stats_in,
    const float* __restrict__ gamma, const float* __restrict__ beta,
    float invn, float* __restrict__ stats1, float* __restrict__ out, int N)
{
    __shared__ float sscale[128], sshift[128];
    if (threadIdx.x < 128) {
        int c = threadIdx.x;
        float mean = stats_in[c] * invn;
        float var = stats_in[128 + c] * invn - mean * mean;
        float inv = rsqrtf(var + 1e-5f);
        float sc = gamma[c] * inv;
        sscale[c] = sc;
        sshift[c] = beta[c] - mean * sc;
    }
    if (blockIdx.x == 0) stats1[threadIdx.x] = 0.f;
    __syncthreads();
    int total4 = N * 32;
    for (int idx = blockIdx.x * blockDim.x + threadIdx.x; idx < total4;
         idx += gridDim.x * blockDim.x) {
        int c4 = (idx & 31) * 4;
        float4 v = *(const float4*)&t2[(long long)idx * 4];
        float4 sc = *(const float4*)&sscale[c4];
        float4 sh = *(const float4*)&sshift[c4];
        float4 o;
        o.x = fmaxf(fmaf(v.x, sc.x, sh.x), 0.f);
        o.y = fmaxf(fmaf(v.y, sc.y, sh.y), 0.f);
        o.z = fmaxf(fmaf(v.z, sc.z, sh.z), 0.f);
        o.w = fmaxf(fmaf(v.w, sc.w, sh.w), 0.f);
        *(float4*)&out[(long long)idx * 4] = o;
    }
}

// ---------------- launch ----------------
extern "C" void kernel_launch(void* const* d_in, const int* in_sizes, int n_in,
                              void* d_out, int out_size)
{
    const float* h        = (const float*)d_in[0];
    const void*  ei       = d_in[1];
    const float* attr     = (const float*)d_in[2];
    const float* ee_w1    = (const float*)d_in[3];
    const float* ee_b1    = (const float*)d_in[4];
    const float* ee_g1    = (const float*)d_in[5];
    const float* ee_bb1   = (const float*)d_in[6];
    const float* ee_w2    = (const float*)d_in[7];
    const float* ee_b2    = (const float*)d_in[8];
    const float* mlp_w1   = (const float*)d_in[9];
    const float* mlp_b1   = (const float*)d_in[10];
    const float* mlp_g1   = (const float*)d_in[11];
    const float* mlp_bb1  = (const float*)d_in[12];
    const float* mlp_w2   = (const float*)d_in[13];
    const float* mlp_b2   = (const float*)d_in[14];
    const float* mlp_g2   = (const float*)d_in[15];
    const float* mlp_bb2  = (const float*)d_in[16];

    int N = in_sizes[0] / D;
    int E = in_sizes[1] / 2;
    float* out = (float*)d_out;

    float *p_agg, *p_deg, *p_hnew, *p_neigh, *p_t1, *p_t2, *p_stats, *p_mom, *p_scale, *p_shift;
    int *p_count, *p_rowptr, *p_next, *p_partial;
    int2 *p_pair;
    cudaGetSymbolAddress((void**)&p_agg, g_agg);
    cudaGetSymbolAddress((void**)&p_deg, g_deg);
    cudaGetSymbolAddress((void**)&p_hnew, g_hnew);
    cudaGetSymbolAddress((void**)&p_neigh, g_neigh);
    cudaGetSymbolAddress((void**)&p_t1, g_t1);
    cudaGetSymbolAddress((void**)&p_t2, g_t2);
    cudaGetSymbolAddress((void**)&p_stats, g_stats);
    cudaGetSymbolAddress((void**)&p_mom, g_mom);
    cudaGetSymbolAddress((void**)&p_scale, g_scale);
    cudaGetSymbolAddress((void**)&p_shift, g_shift);
    cudaGetSymbolAddress((void**)&p_count, g_count);
    cudaGetSymbolAddress((void**)&p_rowptr, g_rowptr);
    cudaGetSymbolAddress((void**)&p_next, g_next);
    cudaGetSymbolAddress((void**)&p_pair, g_pair);
    cudaGetSymbolAddress((void**)&p_partial, g_partial);

    cudaFuncSetAttribute(gemm128<0,0>, cudaFuncAttributeMaxDynamicSharedMemorySize, GEMM_SMEM);
    cudaFuncSetAttribute(gemm128<1,1>, cudaFuncAttributeMaxDynamicSharedMemorySize, GEMM_SMEM);
    cudaFuncSetAttribute(gemm128<2,1>, cudaFuncAttributeMaxDynamicSharedMemorySize, GEMM_SMEM);

    int tiles = (N + 127) / 128;
    int nscan = (N + SCAN_C - 1) / SCAN_C;
    int ngather = (N + 7) / 8;

    // fused edge moments + dst histogram (also zeroes BN2 stats for this replay)
    edge_moments_hist<<<1184, 256>>>(attr, ei, E, N, p_mom, p_count, p_stats + 512);
    finalize_ee_bn<<<1, 128>>>(p_mom, ee_w1, ee_b1, ee_g1, ee_bb1,
                               1.0f / (float)E, p_scale, p_shift);

    // CSR build (by dst)
    scan_partials<<<nscan, 256>>>(p_count, N, p_partial);
    scan_block<<<1, 64>>>(p_partial, nscan);
    scan_write<<<nscan, 256>>>(p_count, p_partial, N, p_rowptr, p_next, p_deg);
    csr_fill<<<1184, 256>>>(ei, E, N, p_next, p_pair);

    // agg = segment_sum(relu(BN(attr@W1)), dst)
    agg_gather<<<ngather, 256>>>(attr, p_rowptr, p_deg, p_pair,
                                 ee_w1, ee_b1, p_scale, p_shift, N, p_agg);

    // h_new = h + agg@ee_w2 + deg*ee_b2
    gemm128<0,0><<<tiles, 256, GEMM_SMEM>>>(p_agg, nullptr, ee_w2, ee_b2,
                                            nullptr, nullptr, nullptr, 0.f,
                                            h, p_deg, p_hnew, nullptr, N);

    // neigh = segment_sum(h_new[src], dst)
    neigh_gather<<<ngather, 256>>>(p_hnew, p_rowptr, p_deg, p_pair, N, p_neigh);

    // t1 = (h_new + neigh) @ mlp_w1 + b1   (+ fused BN1 colstats)
    gemm128<1,1><<<tiles, 256, GEMM_SMEM>>>(p_hnew, p_neigh, mlp_w1, mlp_b1,
                                            nullptr, nullptr, nullptr, 0.f,
                                            nullptr, nullptr, p_t1,
                                            p_stats + 256, N);

    // t2 = relu(bn1(t1)) @ mlp_w2 + b2  (BN1 finalize inlined; + BN2 colstats)
    gemm128<2,1><<<tiles, 256, GEMM_SMEM>>>(p_t1, nullptr, mlp_w2, mlp_b2,
                                            p_stats + 256, mlp_g1, mlp_bb1,
                                            1.0f / (float)N,
                                            nullptr, nullptr, p_t2,
                                            p_stats + 512, N);

    // out = relu(bn2(t2))  (BN2 finalize inlined; zeroes BN1 stats for next replay)
    int g = min((N * 32 + 255) / 256, 4096);
    bn_relu_out<<<g, 256>>>(p_t2, p_stats + 512, mlp_g2, mlp_bb2,
                            1.0f / (float)N, p_stats + 256, out, N);
}